// round 3
// baseline (speedup 1.0000x reference)
#include <cuda_runtime.h>
#include <cuda_bf16.h>
#include <cstdint>

// Problem constants
#define KPOLY 20000
#define PMAX 30
#define NUM_PTS 5
#define C1 112      // conv1 out channels
#define C2 224      // conv2 out channels
#define PE_DIM 32
#define GEO_DIM 256
#define NUM_FREQS 8

#define NB 8                 // polylines per block in conv kernel
#define W2_STRIDE 169        // padded smem row stride for one output channel's 168 weights

typedef unsigned long long ull;

// packed f32x2 FMA: acc.lo += a.lo*b.lo ; acc.hi += a.hi*b.hi
#define FMA2(accv, av, bv) \
    asm("fma.rn.f32x2 %0, %1, %2, %0;" : "+l"(accv) : "l"(av), "l"(bv))

#define PACK2(dst, x, y) \
    asm("mov.b64 %0, {%1, %2};" : "=l"(dst) : "f"(x), "f"(y))

#define UNPACK2(lo, hi, src) \
    asm("mov.b64 {%0, %1}, %2;" : "=f"(lo), "=f"(hi) : "l"(src))

// scratch: normalized coords [K,5,2] produced by kernel1, consumed by kernel2
__device__ float g_coords[KPOLY * NUM_PTS * 2];

__device__ __forceinline__ float scalar_as_float(const void* p) {
    // roi_w / roi_h may arrive as int32 or float32 scalars; disambiguate by bit pattern.
    int iv = *(const int*)p;
    if (iv > 0 && iv < 100000) return (float)iv;
    return *(const float*)p;
}

// ---------------------------------------------------------------------------
// Kernel 1: resample + normalized coords + sinusoidal PE
// one thread per polyline
// ---------------------------------------------------------------------------
__global__ __launch_bounds__(256) void k_resample_pe(
    const float* __restrict__ geoms,     // [K,30,2]
    const int*   __restrict__ lengths,   // [K]
    const void*  __restrict__ roiw_p,
    const void*  __restrict__ roih_p,
    float* __restrict__ out,             // d_out base (geo_feats at offset 0)
    int write_coords)                    // whether d_out has room for coords tail
{
    int k = blockIdx.x * blockDim.x + threadIdx.x;
    if (k >= KPOLY) return;

    float cx[PMAX], cy[PMAX];
    const float* g = geoms + (size_t)k * (PMAX * 2);
#pragma unroll
    for (int i = 0; i < PMAX; i++) { cx[i] = g[2 * i]; cy[i] = g[2 * i + 1]; }

    int L = lengths[k];

    // cumulative arclength, matching jnp: seg = sqrt(sq) if sq>0 else 0, masked; serial cumsum
    float cum[PMAX];
    cum[0] = 0.0f;
    float run = 0.0f;
#pragma unroll
    for (int i = 0; i < PMAX - 1; i++) {
        float dx = cx[i + 1] - cx[i];
        float dy = cy[i + 1] - cy[i];
        float sq = dx * dx + dy * dy;
        float s = (sq > 0.0f) ? sqrtf(sq) : 0.0f;
        if (i >= L - 1) s = 0.0f;
        run += s;
        cum[i + 1] = run;
    }
    float total = run;
    bool degen = total < 1e-6f;

    float roiW = scalar_as_float(roiw_p);
    float roiH = scalar_as_float(roih_p);
    float hx = roiW * 0.5f, hy = roiH * 0.5f;

    const float tv[NUM_PTS] = {0.0f, 0.25f, 0.5f, 0.75f, 1.0f};

#pragma unroll
    for (int j = 0; j < NUM_PTS; j++) {
        float t = tv[j] * total;
        // searchsorted(cum, t, side='left'): first i with cum[i] >= t
        int idx = PMAX;
#pragma unroll
        for (int i = PMAX - 1; i >= 0; i--) {
            if (cum[i] >= t) idx = i;
        }
        idx = max(1, min(idx, L - 1));

        float dx = cx[idx] - cx[idx - 1];
        float dy = cy[idx] - cy[idx - 1];
        float sq = dx * dx + dy * dy;
        float s = (sq > 0.0f) ? sqrtf(sq) : 0.0f;
        float tt = (t - cum[idx - 1]) / (s + 1e-8f);
        float px = cx[idx - 1] + tt * dx;
        float py = cy[idx - 1] + tt * dy;
        if (degen) { px = cx[0]; py = cy[0]; }

        float ux = (px + hx) / roiW;
        float uy = (py + hy) / roiH;

        size_t row = (size_t)k * NUM_PTS + j;
        g_coords[row * 2 + 0] = ux;
        g_coords[row * 2 + 1] = uy;
        if (write_coords) {
            float* oc = out + (size_t)KPOLY * NUM_PTS * GEO_DIM;
            oc[row * 2 + 0] = ux;
            oc[row * 2 + 1] = uy;
        }

        // PE: sin(x * 2^f * pi) = sinpi(x * 2^f)  (exact power-of-two arg scaling)
        float* pe = out + row * GEO_DIM;
        float a = ux;
#pragma unroll
        for (int f = 0; f < NUM_FREQS; f++) {
            float sn, cs;
            sincospif(a, &sn, &cs);
            pe[f] = sn;
            pe[8 + f] = cs;
            a *= 2.0f;
        }
        a = uy;
#pragma unroll
        for (int f = 0; f < NUM_FREQS; f++) {
            float sn, cs;
            sincospif(a, &sn, &cs);
            pe[16 + f] = sn;
            pe[24 + f] = cs;
            a *= 2.0f;
        }
    }
}

// ---------------------------------------------------------------------------
// Kernel 2: conv1 -> relu -> conv2 -> relu -> LayerNorm, 224 threads = out chans,
// NB=8 polylines per block, packed f32x2 accumulation over polyline pairs.
// ---------------------------------------------------------------------------
// dynamic smem layout (floats):
//  s_w2 : 224*169 = 37856   (chunk of conv2 weights; later overlaid by s_y 8960)
//  s_h1 : 112*5*8 = 4480    layout [c][p][b]
//  s_w1 : 672
//  s_b1 : 112
//  s_xy : 80                [b][p][2]
//  s_mu : 40
//  s_var: 40
#define SMEM_FLOATS (224 * W2_STRIDE + 4480 + 672 + 112 + 80 + 40 + 40)

__global__ __launch_bounds__(C2, 1) void k_conv_ln(
    const float* __restrict__ w1g,   // [112,2,3]
    const float* __restrict__ b1g,   // [112]
    const float* __restrict__ w2g,   // [224,112,3]
    const float* __restrict__ b2g,   // [224]
    const float* __restrict__ gg,    // gamma [224]
    const float* __restrict__ btg,   // beta [224]
    float* __restrict__ out)         // geo_feats base
{
    extern __shared__ float sm[];
    float* s_w2 = sm;
    float* s_h1 = s_w2 + 224 * W2_STRIDE;
    float* s_w1 = s_h1 + 4480;
    float* s_b1 = s_w1 + 672;
    float* s_xy = s_b1 + 112;
    float* s_mu = s_xy + 80;
    float* s_var = s_mu + 40;
    float* s_y = s_w2;  // overlay after conv done

    const int tid = threadIdx.x;
    const int o = tid;  // output channel
    const int k0 = blockIdx.x * NB;

    // stage w1, b1, coords; stage w2 chunk 0 ([o][j] j in [0,168), padded stride)
    for (int i = tid; i < 672; i += C2) s_w1[i] = w1g[i];
    if (tid < 112) s_b1[tid] = b1g[tid];
    for (int i = tid; i < NB * NUM_PTS * 2; i += C2) s_xy[i] = g_coords[(size_t)k0 * NUM_PTS * 2 + i];
    for (int i = tid; i < 224 * 168; i += C2) {
        int oo = i / 168, j = i % 168;
        s_w2[oo * W2_STRIDE + j] = w2g[oo * 336 + j];
    }
    __syncthreads();

    // conv1 + relu -> s_h1[c][p][b]
    for (int i = tid; i < NB * C1 * NUM_PTS; i += C2) {
        int b = i / (C1 * NUM_PTS);
        int r = i % (C1 * NUM_PTS);
        int c = r / NUM_PTS;
        int p = r % NUM_PTS;
        float h = s_b1[c];
#pragma unroll
        for (int t = 0; t < 3; t++) {
            int pp = p + t - 1;
            if (pp >= 0 && pp < NUM_PTS) {
                h += s_xy[(b * NUM_PTS + pp) * 2 + 0] * s_w1[(c * 2 + 0) * 3 + t];
                h += s_xy[(b * NUM_PTS + pp) * 2 + 1] * s_w1[(c * 2 + 1) * 3 + t];
            }
        }
        s_h1[(c * NUM_PTS + p) * NB + b] = fmaxf(h, 0.0f);
    }
    __syncthreads();

    float bias2 = b2g[o];
    float gm = gg[o];
    float bt = btg[o];

    ull acc[4][NUM_PTS];
#pragma unroll
    for (int j = 0; j < 4; j++)
#pragma unroll
        for (int p = 0; p < NUM_PTS; p++) acc[j][p] = 0ull;

    const float* wrow = s_w2 + o * W2_STRIDE;

#pragma unroll 1
    for (int ch = 0; ch < 2; ch++) {
        if (ch == 1) {
            __syncthreads();
            for (int i = tid; i < 224 * 168; i += C2) {
                int oo = i / 168, j = i % 168;
                s_w2[oo * W2_STRIDE + j] = w2g[oo * 336 + 168 + j];
            }
            __syncthreads();
        }
#pragma unroll 4
        for (int cc = 0; cc < 56; cc++) {
            float w0 = wrow[cc * 3 + 0];
            float w1_ = wrow[cc * 3 + 1];
            float w2_ = wrow[cc * 3 + 2];
            ull W0, W1, W2;
            PACK2(W0, w0, w0);
            PACK2(W1, w1_, w1_);
            PACK2(W2, w2_, w2_);
            const int c = ch * 56 + cc;
            const ull* hp = ((const ull*)s_h1) + c * (NUM_PTS * NB / 2);
#pragma unroll
            for (int j = 0; j < 4; j++) {
                ull h0 = hp[0 * 4 + j];
                ull h1 = hp[1 * 4 + j];
                ull h2 = hp[2 * 4 + j];
                ull h3 = hp[3 * 4 + j];
                ull h4 = hp[4 * 4 + j];
                FMA2(acc[j][0], h0, W1); FMA2(acc[j][0], h1, W2);
                FMA2(acc[j][1], h0, W0); FMA2(acc[j][1], h1, W1); FMA2(acc[j][1], h2, W2);
                FMA2(acc[j][2], h1, W0); FMA2(acc[j][2], h2, W1); FMA2(acc[j][2], h3, W2);
                FMA2(acc[j][3], h2, W0); FMA2(acc[j][3], h3, W1); FMA2(acc[j][3], h4, W2);
                FMA2(acc[j][4], h3, W0); FMA2(acc[j][4], h4, W1);
            }
        }
    }
    __syncthreads();  // done reading s_w2; overlay s_y

    // bias + relu -> s_y[(b*5+p)*224 + o]
#pragma unroll
    for (int j = 0; j < 4; j++) {
#pragma unroll
        for (int p = 0; p < NUM_PTS; p++) {
            float ya, yb;
            UNPACK2(ya, yb, acc[j][p]);
            ya = fmaxf(ya + bias2, 0.0f);
            yb = fmaxf(yb + bias2, 0.0f);
            s_y[((2 * j) * NUM_PTS + p) * C2 + o] = ya;
            s_y[((2 * j + 1) * NUM_PTS + p) * C2 + o] = yb;
        }
    }
    __syncthreads();

    // LayerNorm stats per (b,p): 40 rows of 224
    {
        int w = tid >> 5, l = tid & 31;
        for (int r = w; r < NB * NUM_PTS; r += 7) {
            float s = 0.0f, q = 0.0f;
            for (int i = l; i < C2; i += 32) {
                float v = s_y[r * C2 + i];
                s += v;
                q += v * v;
            }
#pragma unroll
            for (int d = 16; d > 0; d >>= 1) {
                s += __shfl_xor_sync(0xffffffffu, s, d);
                q += __shfl_xor_sync(0xffffffffu, q, d);
            }
            if (l == 0) {
                float mu = s * (1.0f / 224.0f);
                s_mu[r] = mu;
                s_var[r] = fmaxf(q * (1.0f / 224.0f) - mu * mu, 0.0f);
            }
        }
    }
    __syncthreads();

    // normalize + write out
#pragma unroll 1
    for (int r = 0; r < NB * NUM_PTS; r++) {
        int b = r / NUM_PTS, p = r % NUM_PTS;
        float x = s_y[r * C2 + o];
        float inv = rsqrtf(s_var[r] + 1e-5f);
        float v = (x - s_mu[r]) * inv * gm + bt;
        out[((size_t)(k0 + b) * NUM_PTS + p) * GEO_DIM + PE_DIM + o] = v;
    }
}

// ---------------------------------------------------------------------------
extern "C" void kernel_launch(void* const* d_in, const int* in_sizes, int n_in,
                              void* d_out, int out_size) {
    const float* geoms  = (const float*)d_in[0];
    const int*   lengths = (const int*)d_in[1];
    const float* w1 = (const float*)d_in[2];
    const float* b1 = (const float*)d_in[3];
    const float* w2 = (const float*)d_in[4];
    const float* b2 = (const float*)d_in[5];
    const float* gamma = (const float*)d_in[6];
    const float* beta  = (const float*)d_in[7];
    const void*  roiw = d_in[8];
    const void*  roih = d_in[9];
    float* out = (float*)d_out;

    const long long geo_elems = (long long)KPOLY * NUM_PTS * GEO_DIM;           // 25,600,000
    const long long full_elems = geo_elems + (long long)KPOLY * NUM_PTS * 2;    // 25,800,000
    int write_coords = (out_size >= full_elems) ? 1 : 0;

    k_resample_pe<<<(KPOLY + 255) / 256, 256>>>(geoms, lengths, roiw, roih, out, write_coords);

    static int smem_set = 0;
    size_t smem_bytes = (size_t)SMEM_FLOATS * sizeof(float);
    if (!smem_set) {
        cudaFuncSetAttribute(k_conv_ln, cudaFuncAttributeMaxDynamicSharedMemorySize, (int)smem_bytes);
        smem_set = 1;
    }
    k_conv_ln<<<KPOLY / NB, C2, smem_bytes>>>(w1, b1, w2, b2, gamma, beta, out);
}

// round 4
// speedup vs baseline: 1.9127x; 1.9127x over previous
#include <cuda_runtime.h>
#include <cuda_bf16.h>
#include <cstdint>

// Problem constants
#define KPOLY 20000
#define PMAX 30
#define NUM_PTS 5
#define C1 112      // conv1 out channels
#define C2 224      // conv2 out channels
#define PE_DIM 32
#define GEO_DIM 256
#define NUM_FREQS 8

#define NB 16                // polylines per block in conv kernel
#define NPAIR (NB / 2)       // f32x2 polyline pairs

typedef unsigned long long ull;

// packed f32x2 FMA: acc.lo += a.lo*b.lo ; acc.hi += a.hi*b.hi
#define FMA2(accv, av, bv) \
    asm("fma.rn.f32x2 %0, %1, %2, %0;" : "+l"(accv) : "l"(av), "l"(bv))

#define PACK2(dst, x, y) \
    asm("mov.b64 %0, {%1, %2};" : "=l"(dst) : "f"(x), "f"(y))

#define UNPACK2(lo, hi, src) \
    asm("mov.b64 {%0, %1}, %2;" : "=f"(lo), "=f"(hi) : "l"(src))

// scratch: normalized coords [K,5,2] produced by kernel1, consumed by kernel2
__device__ float g_coords[KPOLY * NUM_PTS * 2];
// transposed conv2 weights: w2t[j][o] = w2[o][j], j in [0,336)
__device__ float g_w2t[336 * C2];

__device__ __forceinline__ float scalar_as_float(const void* p) {
    int iv = *(const int*)p;
    if (iv > 0 && iv < 100000) return (float)iv;
    return *(const float*)p;
}

// ---------------------------------------------------------------------------
// Kernel 0: transpose w2 [224,336] -> [336,224] for coalesced weight reads
// ---------------------------------------------------------------------------
__global__ __launch_bounds__(256) void k_transpose_w2(const float* __restrict__ w2g) {
    int i = blockIdx.x * blockDim.x + threadIdx.x;
    if (i < 336 * C2) {
        int j = i / C2, o = i % C2;
        g_w2t[i] = w2g[o * 336 + j];
    }
}

// ---------------------------------------------------------------------------
// Kernel 1: resample + normalized coords + sinusoidal PE (one thread/polyline)
// ---------------------------------------------------------------------------
__global__ __launch_bounds__(256) void k_resample_pe(
    const float* __restrict__ geoms,     // [K,30,2]
    const int*   __restrict__ lengths,   // [K]
    const void*  __restrict__ roiw_p,
    const void*  __restrict__ roih_p,
    float* __restrict__ out,             // d_out base (geo_feats at offset 0)
    int write_coords)
{
    int k = blockIdx.x * blockDim.x + threadIdx.x;
    if (k >= KPOLY) return;

    float cx[PMAX], cy[PMAX];
    const float* g = geoms + (size_t)k * (PMAX * 2);
#pragma unroll
    for (int i = 0; i < PMAX; i++) { cx[i] = g[2 * i]; cy[i] = g[2 * i + 1]; }

    int L = lengths[k];

    float cum[PMAX];
    cum[0] = 0.0f;
    float run = 0.0f;
#pragma unroll
    for (int i = 0; i < PMAX - 1; i++) {
        float dx = cx[i + 1] - cx[i];
        float dy = cy[i + 1] - cy[i];
        float sq = dx * dx + dy * dy;
        float s = (sq > 0.0f) ? sqrtf(sq) : 0.0f;
        if (i >= L - 1) s = 0.0f;
        run += s;
        cum[i + 1] = run;
    }
    float total = run;
    bool degen = total < 1e-6f;

    float roiW = scalar_as_float(roiw_p);
    float roiH = scalar_as_float(roih_p);
    float hx = roiW * 0.5f, hy = roiH * 0.5f;

    const float tv[NUM_PTS] = {0.0f, 0.25f, 0.5f, 0.75f, 1.0f};

#pragma unroll
    for (int j = 0; j < NUM_PTS; j++) {
        float t = tv[j] * total;
        int idx = PMAX;
#pragma unroll
        for (int i = PMAX - 1; i >= 0; i--) {
            if (cum[i] >= t) idx = i;
        }
        idx = max(1, min(idx, L - 1));

        float dx = cx[idx] - cx[idx - 1];
        float dy = cy[idx] - cy[idx - 1];
        float sq = dx * dx + dy * dy;
        float s = (sq > 0.0f) ? sqrtf(sq) : 0.0f;
        float tt = (t - cum[idx - 1]) / (s + 1e-8f);
        float px = cx[idx - 1] + tt * dx;
        float py = cy[idx - 1] + tt * dy;
        if (degen) { px = cx[0]; py = cy[0]; }

        float ux = (px + hx) / roiW;
        float uy = (py + hy) / roiH;

        size_t row = (size_t)k * NUM_PTS + j;
        g_coords[row * 2 + 0] = ux;
        g_coords[row * 2 + 1] = uy;
        if (write_coords) {
            float* oc = out + (size_t)KPOLY * NUM_PTS * GEO_DIM;
            oc[row * 2 + 0] = ux;
            oc[row * 2 + 1] = uy;
        }

        float* pe = out + row * GEO_DIM;
        float a = ux;
#pragma unroll
        for (int f = 0; f < NUM_FREQS; f++) {
            float sn, cs;
            sincospif(a, &sn, &cs);
            pe[f] = sn;
            pe[8 + f] = cs;
            a *= 2.0f;
        }
        a = uy;
#pragma unroll
        for (int f = 0; f < NUM_FREQS; f++) {
            float sn, cs;
            sincospif(a, &sn, &cs);
            pe[16 + f] = sn;
            pe[24 + f] = cs;
            a *= 2.0f;
        }
    }
}

// ---------------------------------------------------------------------------
// Kernel 2: conv1 -> relu -> conv2 -> relu -> LayerNorm
// 224 threads = output channels, NB=16 polylines/block.
// Conv2 weights read via coalesced LDG from transposed global (L2-resident).
// smem only holds h1 (during conv) / y (after conv) + small constants.
// ---------------------------------------------------------------------------
// smem layout (floats):
//  region A [0, 17920): s_h1 (112*5*16=8960) during conv; s_y (16*5*224) after
//  then: s_w1 672, s_b1 112, s_xy 160, s_mu 80, s_inv 80
#define SM_A 17920
#define SMEM_FLOATS (SM_A + 672 + 112 + 160 + 80 + 80)

__global__ __launch_bounds__(C2, 2) void k_conv_ln(
    const float* __restrict__ w1g,   // [112,2,3]
    const float* __restrict__ b1g,   // [112]
    const float* __restrict__ b2g,   // [224]
    const float* __restrict__ gg,    // gamma [224]
    const float* __restrict__ btg,   // beta [224]
    float* __restrict__ out)         // geo_feats base
{
    extern __shared__ float sm[];
    float* s_h1  = sm;          // during conv
    float* s_y   = sm;          // after conv (overlay)
    float* s_w1  = sm + SM_A;
    float* s_b1  = s_w1 + 672;
    float* s_xy  = s_b1 + 112;
    float* s_mu  = s_xy + 160;
    float* s_inv = s_mu + 80;

    const int tid = threadIdx.x;
    const int o = tid;
    const int k0 = blockIdx.x * NB;

    // stage small constants + coords
    for (int i = tid; i < 672; i += C2) s_w1[i] = w1g[i];
    if (tid < 112) s_b1[tid] = b1g[tid];
    for (int i = tid; i < NB * NUM_PTS * 2; i += C2)
        s_xy[i] = g_coords[(size_t)k0 * NUM_PTS * 2 + i];
    __syncthreads();

    // conv1 + relu -> s_h1[c][p][b]   (16*112*5 = 8960 items, 40/thread)
    for (int i = tid; i < NB * C1 * NUM_PTS; i += C2) {
        int b = i / (C1 * NUM_PTS);
        int r = i % (C1 * NUM_PTS);
        int c = r / NUM_PTS;
        int p = r % NUM_PTS;
        float h = s_b1[c];
#pragma unroll
        for (int t = 0; t < 3; t++) {
            int pp = p + t - 1;
            if (pp >= 0 && pp < NUM_PTS) {
                h += s_xy[(b * NUM_PTS + pp) * 2 + 0] * s_w1[(c * 2 + 0) * 3 + t];
                h += s_xy[(b * NUM_PTS + pp) * 2 + 1] * s_w1[(c * 2 + 1) * 3 + t];
            }
        }
        s_h1[(c * NUM_PTS + p) * NB + b] = fmaxf(h, 0.0f);
    }
    __syncthreads();

    // conv2 accumulation: single pass over all 112 input channels.
    // Weights via coalesced LDG (stride-224 rows of g_w2t), h via broadcast LDS.64.
    ull acc[NPAIR][NUM_PTS];
#pragma unroll
    for (int j = 0; j < NPAIR; j++)
#pragma unroll
        for (int p = 0; p < NUM_PTS; p++) acc[j][p] = 0ull;

    const float* wp = g_w2t + o;   // wp[(c*3+t)*C2]

#pragma unroll 2
    for (int c = 0; c < C1; c++) {
        float w0  = __ldg(wp + (c * 3 + 0) * C2);
        float w1_ = __ldg(wp + (c * 3 + 1) * C2);
        float w2_ = __ldg(wp + (c * 3 + 2) * C2);
        ull W0, W1, W2;
        PACK2(W0, w0, w0);
        PACK2(W1, w1_, w1_);
        PACK2(W2, w2_, w2_);
        const ull* hp = ((const ull*)s_h1) + c * (NUM_PTS * NPAIR);
#pragma unroll
        for (int j = 0; j < NPAIR; j++) {
            ull h0 = hp[0 * NPAIR + j];
            ull h1 = hp[1 * NPAIR + j];
            ull h2 = hp[2 * NPAIR + j];
            ull h3 = hp[3 * NPAIR + j];
            ull h4 = hp[4 * NPAIR + j];
            FMA2(acc[j][0], h0, W1); FMA2(acc[j][0], h1, W2);
            FMA2(acc[j][1], h0, W0); FMA2(acc[j][1], h1, W1); FMA2(acc[j][1], h2, W2);
            FMA2(acc[j][2], h1, W0); FMA2(acc[j][2], h2, W1); FMA2(acc[j][2], h3, W2);
            FMA2(acc[j][3], h2, W0); FMA2(acc[j][3], h3, W1); FMA2(acc[j][3], h4, W2);
            FMA2(acc[j][4], h3, W0); FMA2(acc[j][4], h4, W1);
        }
    }
    __syncthreads();  // all warps done reading s_h1; overlay s_y

    // bias + relu -> s_y[(b*5+p)*224 + o]
    float bias2 = b2g[o];
#pragma unroll
    for (int j = 0; j < NPAIR; j++) {
#pragma unroll
        for (int p = 0; p < NUM_PTS; p++) {
            float ya, yb;
            UNPACK2(ya, yb, acc[j][p]);
            ya = fmaxf(ya + bias2, 0.0f);
            yb = fmaxf(yb + bias2, 0.0f);
            s_y[((2 * j) * NUM_PTS + p) * C2 + o] = ya;
            s_y[((2 * j + 1) * NUM_PTS + p) * C2 + o] = yb;
        }
    }
    __syncthreads();

    // LayerNorm stats per (b,p): 80 rows of 224; store mu and rsqrt(var+eps)
    {
        int w = tid >> 5, l = tid & 31;
        for (int r = w; r < NB * NUM_PTS; r += 7) {
            float s = 0.0f, q = 0.0f;
            for (int i = l; i < C2; i += 32) {
                float v = s_y[r * C2 + i];
                s += v;
                q += v * v;
            }
#pragma unroll
            for (int d = 16; d > 0; d >>= 1) {
                s += __shfl_xor_sync(0xffffffffu, s, d);
                q += __shfl_xor_sync(0xffffffffu, q, d);
            }
            if (l == 0) {
                float mu = s * (1.0f / 224.0f);
                float var = fmaxf(q * (1.0f / 224.0f) - mu * mu, 0.0f);
                s_mu[r] = mu;
                s_inv[r] = rsqrtf(var + 1e-5f);
            }
        }
    }
    __syncthreads();

    // normalize + write out (coalesced across o)
    float gm = gg[o];
    float bt = btg[o];
    float* obase = out + ((size_t)k0 * NUM_PTS) * GEO_DIM + PE_DIM + o;
#pragma unroll 4
    for (int r = 0; r < NB * NUM_PTS; r++) {
        float x = s_y[r * C2 + o];
        float v = (x - s_mu[r]) * s_inv[r] * gm + bt;
        obase[(size_t)r * GEO_DIM] = v;
    }
}

// ---------------------------------------------------------------------------
extern "C" void kernel_launch(void* const* d_in, const int* in_sizes, int n_in,
                              void* d_out, int out_size) {
    const float* geoms  = (const float*)d_in[0];
    const int*   lengths = (const int*)d_in[1];
    const float* w1 = (const float*)d_in[2];
    const float* b1 = (const float*)d_in[3];
    const float* w2 = (const float*)d_in[4];
    const float* b2 = (const float*)d_in[5];
    const float* gamma = (const float*)d_in[6];
    const float* beta  = (const float*)d_in[7];
    const void*  roiw = d_in[8];
    const void*  roih = d_in[9];
    float* out = (float*)d_out;

    const long long geo_elems = (long long)KPOLY * NUM_PTS * GEO_DIM;           // 25,600,000
    const long long full_elems = geo_elems + (long long)KPOLY * NUM_PTS * 2;    // 25,800,000
    int write_coords = (out_size >= full_elems) ? 1 : 0;

    k_transpose_w2<<<(336 * C2 + 255) / 256, 256>>>(w2);
    k_resample_pe<<<(KPOLY + 255) / 256, 256>>>(geoms, lengths, roiw, roih, out, write_coords);

    static int smem_set = 0;
    size_t smem_bytes = (size_t)SMEM_FLOATS * sizeof(float);
    if (!smem_set) {
        cudaFuncSetAttribute(k_conv_ln, cudaFuncAttributeMaxDynamicSharedMemorySize, (int)smem_bytes);
        smem_set = 1;
    }
    k_conv_ln<<<KPOLY / NB, C2, smem_bytes>>>(w1, b1, b2, gamma, beta, out);
}